// round 2
// baseline (speedup 1.0000x reference)
#include <cuda_runtime.h>

// AttentionOutput: causal complex-score leaky-relu attention + linear head.
// B=4, N=4096, F=64. fp32 SIMT baseline (round 1).

#define BM 32      // query rows per CTA
#define BN 64      // key cols per tile
#define FD 64      // feature dim
#define NT 256     // threads per CTA
#define KSTR 66    // Ks row stride in float2 (even pad: 16B-aligned LDS.128, bank-spread)

// Shared memory layout (bytes):
//   Qs [BM][FD]   float2 : 16384
//   Ks [FD][KSTR] float2 : 33792   (K transposed, k-major)
//   Vs [BN][FD]   float2 : 32768   (reused as W [64][65] float in epilogue)
//   Ss [BM][FD]   float2 : 16384   (scores; reused as O accumulator buffer)
#define SM_Q 0
#define SM_K 16384
#define SM_V (16384 + 33792)
#define SM_S (16384 + 33792 + 32768)
#define SM_TOTAL (16384 + 33792 + 32768 + 16384)   // 99328 B -> 2 CTAs/SM

__global__ __launch_bounds__(NT, 2)
void attn_out_kernel(const float2* __restrict__ Qg,
                     const float2* __restrict__ Kg,
                     const float2* __restrict__ Vg,
                     const float*  __restrict__ Wg,
                     const float*  __restrict__ bg,
                     float2* __restrict__ Og,
                     int N)
{
    extern __shared__ char smem[];
    float2* Qs = (float2*)(smem + SM_Q);
    float2* Ks = (float2*)(smem + SM_K);
    float2* Vs = (float2*)(smem + SM_V);
    float2* Ss = (float2*)(smem + SM_S);
    float*  Ws = (float*)(smem + SM_V);   // epilogue reuse of Vs

    const int tid   = threadIdx.x;
    const int b     = blockIdx.y;
    const int qtile = (int)gridDim.x - 1 - (int)blockIdx.x;  // heavy tiles first
    const int qi0   = qtile * BM;

    // ---- load Q tile (coalesced float4) ----
    {
        const float4* src = (const float4*)(Qg + ((size_t)b * N + qi0) * FD);
        float4* dst = (float4*)Qs;
        #pragma unroll
        for (int idx = tid; idx < BM * FD / 2; idx += NT) dst[idx] = src[idx];
    }

    // phase-2 / output accumulators: 2 rows x 4 feature slots x {r,i}
    float o_r[2][4], o_i[2][4];
    #pragma unroll
    for (int r = 0; r < 2; ++r)
        #pragma unroll
        for (int m = 0; m < 4; ++m) { o_r[r][m] = 0.f; o_i[r][m] = 0.f; }

    const int p1row = (tid >> 5) << 2;   // phase1: 4 query rows per thread
    const int p1col = (tid & 31) << 1;   // phase1: 2 key cols per thread
    const int p2i   = (tid >> 4) << 1;   // phase2: 2 query rows
    const int p2f   = tid & 15;          // phase2: features {p2f,+16,+32,+48}

    const float scale = 1.0f / 64.0f;    // 1/sqrt(N)
    const int nkt = (qi0 + BM - 1) / BN + 1;

    for (int t = 0; t < nkt; ++t) {
        const int kt = t * BN;
        __syncthreads();   // previous phase-2 done before overwriting Ks/Vs

        // ---- load K (transposed, k-major) and V (row-major) ----
        {
            const float4* Kr4 = (const float4*)(Kg + ((size_t)b * N + kt) * FD);
            const float4* Vr4 = (const float4*)(Vg + ((size_t)b * N + kt) * FD);
            float4* Vd4 = (float4*)Vs;
            #pragma unroll
            for (int idx = tid; idx < BN * FD / 2; idx += NT) {
                float4 kv = Kr4[idx];
                int j  = idx >> 5;           // key row (32 float4 per row)
                int kk = (idx & 31) << 1;    // feature k, k+1
                Ks[(kk    ) * KSTR + j] = make_float2(kv.x, kv.y);
                Ks[(kk + 1) * KSTR + j] = make_float2(kv.z, kv.w);
                Vd4[idx] = Vr4[idx];
            }
        }
        __syncthreads();

        // ---- phase 1: complex scores, 4x2 micro-tile ----
        float sr[4][2], si[4][2];
        #pragma unroll
        for (int r = 0; r < 4; ++r)
            #pragma unroll
            for (int c = 0; c < 2; ++c) { sr[r][c] = 0.f; si[r][c] = 0.f; }

        #pragma unroll 4
        for (int k = 0; k < FD; ++k) {
            // (Kr[j0],Ki[j0],Kr[j0+1],Ki[j0+1]) — one conflict-free LDS.128
            float4 kk4 = *(const float4*)(Ks + k * KSTR + p1col);
            #pragma unroll
            for (int r = 0; r < 4; ++r) {
                float2 q = Qs[(p1row + r) * FD + k];   // broadcast
                sr[r][0] = fmaf(q.x, kk4.x, sr[r][0]);
                sr[r][0] = fmaf(-q.y, kk4.y, sr[r][0]);
                si[r][0] = fmaf(q.x, kk4.y, si[r][0]);
                si[r][0] = fmaf(q.y, kk4.x, si[r][0]);
                sr[r][1] = fmaf(q.x, kk4.z, sr[r][1]);
                sr[r][1] = fmaf(-q.y, kk4.w, sr[r][1]);
                si[r][1] = fmaf(q.x, kk4.w, si[r][1]);
                si[r][1] = fmaf(q.y, kk4.z, si[r][1]);
            }
        }

        // ---- scale + leaky relu + causal mask, store S tile ----
        const bool full = (kt + BN - 1 <= qi0);  // whole tile below diagonal
        #pragma unroll
        for (int r = 0; r < 4; ++r) {
            const int gi = qi0 + p1row + r;
            float w00, w01, w10, w11;
            {
                float vr = sr[r][0] * scale, vi = si[r][0] * scale;
                vr = vr >= 0.f ? vr : 0.01f * vr;
                vi = vi >= 0.f ? vi : 0.01f * vi;
                if (!full && (kt + p1col) > gi) { vr = 0.f; vi = 0.f; }
                w00 = vr; w01 = vi;
            }
            {
                float vr = sr[r][1] * scale, vi = si[r][1] * scale;
                vr = vr >= 0.f ? vr : 0.01f * vr;
                vi = vi >= 0.f ? vi : 0.01f * vi;
                if (!full && (kt + p1col + 1) > gi) { vr = 0.f; vi = 0.f; }
                w10 = vr; w11 = vi;
            }
            *(float4*)(Ss + (p1row + r) * FD + p1col) = make_float4(w00, w01, w10, w11);
        }
        __syncthreads();

        // ---- phase 2: O += w * V (r with r, i with i) ----
        #pragma unroll 4
        for (int j = 0; j < BN; ++j) {
            float2 w0 = Ss[(p2i    ) * FD + j];   // broadcast
            float2 w1 = Ss[(p2i + 1) * FD + j];
            #pragma unroll
            for (int m = 0; m < 4; ++m) {
                float2 v = Vs[j * FD + p2f + 16 * m];  // contiguous per half-warp
                o_r[0][m] = fmaf(w0.x, v.x, o_r[0][m]);
                o_i[0][m] = fmaf(w0.y, v.y, o_i[0][m]);
                o_r[1][m] = fmaf(w1.x, v.x, o_r[1][m]);
                o_i[1][m] = fmaf(w1.y, v.y, o_i[1][m]);
            }
        }
    }

    __syncthreads();   // all phase-2 smem reads done

    // ---- park O in Ss; stage W_att into (dead) Vs region ----
    #pragma unroll
    for (int m = 0; m < 4; ++m) {
        Ss[(p2i    ) * FD + p2f + 16 * m] = make_float2(o_r[0][m], o_i[0][m]);
        Ss[(p2i + 1) * FD + p2f + 16 * m] = make_float2(o_r[1][m], o_i[1][m]);
    }
    for (int idx = tid; idx < FD * FD; idx += NT) {
        int f = idx >> 6, k = idx & 63;
        Ws[f * 65 + k] = Wg[idx];   // 65-stride: conflict-free column reads
    }
    __syncthreads();

    // ---- linear head: out = O @ W^T + b (shared for r and i) ----
    float a_r[2][4], a_i[2][4];
    #pragma unroll
    for (int m = 0; m < 4; ++m) {
        float bb = bg[p2f + 16 * m];
        a_r[0][m] = bb; a_i[0][m] = bb;
        a_r[1][m] = bb; a_i[1][m] = bb;
    }
    #pragma unroll 4
    for (int k = 0; k < FD; ++k) {
        float2 o0 = Ss[(p2i    ) * FD + k];
        float2 o1 = Ss[(p2i + 1) * FD + k];
        #pragma unroll
        for (int m = 0; m < 4; ++m) {
            float w = Ws[(p2f + 16 * m) * 65 + k];
            a_r[0][m] = fmaf(o0.x, w, a_r[0][m]);
            a_i[0][m] = fmaf(o0.y, w, a_i[0][m]);
            a_r[1][m] = fmaf(o1.x, w, a_r[1][m]);
            a_i[1][m] = fmaf(o1.y, w, a_i[1][m]);
        }
    }

    // ---- write output [B,N,F,2] ----
    float2* Orow = Og + ((size_t)b * N + qi0) * FD;
    #pragma unroll
    for (int m = 0; m < 4; ++m) {
        Orow[(p2i    ) * FD + p2f + 16 * m] = make_float2(a_r[0][m], a_i[0][m]);
        Orow[(p2i + 1) * FD + p2f + 16 * m] = make_float2(a_r[1][m], a_i[1][m]);
    }
}

extern "C" void kernel_launch(void* const* d_in, const int* in_sizes, int n_in,
                              void* d_out, int out_size)
{
    const float2* Q = (const float2*)d_in[0];
    const float2* K = (const float2*)d_in[1];
    const float2* V = (const float2*)d_in[2];
    const float*  W = (const float*)d_in[3];
    const float*  bb = (const float*)d_in[4];
    float2* O = (float2*)d_out;

    const int B = 4, N = 4096;

    static bool attr_set = false;
    if (!attr_set) {
        cudaFuncSetAttribute(attn_out_kernel,
                             cudaFuncAttributeMaxDynamicSharedMemorySize, SM_TOTAL);
        attr_set = true;
    }

    dim3 grid(N / BM, B);
    attn_out_kernel<<<grid, NT, SM_TOTAL>>>(Q, K, V, W, bb, O, N);
}

// round 5
// speedup vs baseline: 1.5279x; 1.5279x over previous
#include <cuda_runtime.h>
#include <cstdint>

// AttentionOutput: causal complex leaky-relu attention + linear head.
// B=4, N=4096, F=64.  mma.sync.m16n8k8.tf32 (3xTF32+Karatsuba QK, 2xTF32 PV).

#define NT 256
#define STR 68      // padded stride (floats) for Q/K/W/Watt
#define VSTR 72     // padded stride for V
// smem offsets in floats
#define QR 0
#define QI 4352
#define KR 8704
#define KI 13056
#define VR 17408
#define VI 22016
#define WR 26624
#define WI 30976
#define SMF 35328
#define SMB (SMF * 4)   // 141312 bytes
#define WATT KR
#define BIAS KI

__device__ __forceinline__ float rna(float x) {
    uint32_t u;
    asm("cvt.rna.tf32.f32 %0, %1;" : "=r"(u) : "f"(x));
    return __uint_as_float(u);
}

__device__ __forceinline__ void mma8(float* c, float a0, float a1, float a2, float a3,
                                     float b0, float b1) {
    uint32_t A0 = __float_as_uint(a0), A1 = __float_as_uint(a1);
    uint32_t A2 = __float_as_uint(a2), A3 = __float_as_uint(a3);
    uint32_t B0 = __float_as_uint(b0), B1 = __float_as_uint(b1);
    asm volatile("mma.sync.aligned.m16n8k8.row.col.f32.tf32.tf32.f32 "
                 "{%0,%1,%2,%3},{%4,%5,%6,%7},{%8,%9},{%0,%1,%2,%3};"
                 : "+f"(c[0]), "+f"(c[1]), "+f"(c[2]), "+f"(c[3])
                 : "r"(A0), "r"(A1), "r"(A2), "r"(A3), "r"(B0), "r"(B1));
}

// load A-frag quad (rows g,g+8 x cols t,t+4) from fp32 smem
#define LDQUAD(arr, base, v0, v1, v2, v3)                                   \
    float v0 = sm[(arr) + (base)];                                          \
    float v1 = sm[(arr) + (base) + 8 * STR];                                \
    float v2 = sm[(arr) + (base) + 4];                                      \
    float v3 = sm[(arr) + (base) + 8 * STR + 4];

#define SPLIT4(x0, x1, x2, x3, h0, h1, h2, h3, l0, l1, l2, l3)              \
    float h0 = rna(x0), h1 = rna(x1), h2 = rna(x2), h3 = rna(x3);           \
    float l0 = x0 - h0, l1 = x1 - h1, l2 = x2 - h2, l3 = x3 - h3;

__global__ __launch_bounds__(NT)
void attn_k(const float2* __restrict__ Qg, const float2* __restrict__ Kg,
            const float2* __restrict__ Vg, const float* __restrict__ Wg,
            const float* __restrict__ bg, float2* __restrict__ Og)
{
    extern __shared__ float sm[];
    const int tid = threadIdx.x, w = tid >> 5, l = tid & 31;
    const int g = l >> 2, t = l & 3;
    const int b = blockIdx.y;
    const int qt = (int)gridDim.x - 1 - (int)blockIdx.x;   // heavy tiles first
    const int qi0 = qt * 64;
    const int N = 4096;

    const int i0w = (w >> 1) * 16, j0w = (w & 1) * 32;     // phase-1 warp map
    const int i0p = (w & 3) * 16, f0p = (w >> 2) * 32;     // phase-2 warp map

    // ---- load Q tile (fp32) ----
    {
        const float2* Qp = Qg + ((size_t)b * N + qi0) * 64;
        for (int idx = tid; idx < 64 * 64; idx += NT) {
            float2 q = Qp[idx];
            int a = (idx >> 6) * STR + (idx & 63);
            sm[QR + a] = q.x; sm[QI + a] = q.y;
        }
    }

    float o_r[4][4], o_i[4][4];
    #pragma unroll
    for (int nb = 0; nb < 4; ++nb)
        #pragma unroll
        for (int r = 0; r < 4; ++r) { o_r[nb][r] = 0.f; o_i[nb][r] = 0.f; }

    const float scale = 1.0f / 64.0f;   // 1/sqrt(4096)

    for (int tt = 0; tt <= qt; ++tt) {
        const int kt = tt * 64;
        __syncthreads();   // prior phase-2 reads of V/W done

        // ---- load K (fp32) and V (tf32) ----
        {
            const float2* Kp = Kg + ((size_t)b * N + kt) * 64;
            const float2* Vp = Vg + ((size_t)b * N + kt) * 64;
            for (int idx = tid; idx < 64 * 64; idx += NT) {
                float2 kv = Kp[idx];
                float2 vv = Vp[idx];
                int j = idx >> 6, f = idx & 63;
                sm[KR + j * STR + f] = kv.x;
                sm[KI + j * STR + f] = kv.y;
                sm[VR + j * VSTR + f] = rna(vv.x);
                sm[VI + j * VSTR + f] = rna(vv.y);
            }
        }
        __syncthreads();

        // ---- phase 1: Crr, Cii, Css (Karatsuba, 3xTF32 each) ----
        float crr[4][4], cii[4][4], css[4][4];
        #pragma unroll
        for (int nb = 0; nb < 4; ++nb)
            #pragma unroll
            for (int r = 0; r < 4; ++r) { crr[nb][r] = 0.f; cii[nb][r] = 0.f; css[nb][r] = 0.f; }

        for (int kk = 0; kk < 8; ++kk) {
            const int k0 = kk * 8;
            const int ab = (i0w + g) * STR + k0 + t;
            LDQUAD(QR, ab, xr0, xr1, xr2, xr3)
            LDQUAD(QI, ab, xi0, xi1, xi2, xi3)
            SPLIT4(xr0, xr1, xr2, xr3, qrh0, qrh1, qrh2, qrh3, qrl0, qrl1, qrl2, qrl3)
            SPLIT4(xi0, xi1, xi2, xi3, qih0, qih1, qih2, qih3, qil0, qil1, qil2, qil3)
            float xs0 = xr0 + xi0, xs1 = xr1 + xi1, xs2 = xr2 + xi2, xs3 = xr3 + xi3;
            SPLIT4(xs0, xs1, xs2, xs3, qsh0, qsh1, qsh2, qsh3, qsl0, qsl1, qsl2, qsl3)
            #pragma unroll
            for (int nb = 0; nb < 4; ++nb) {
                const int bb = (j0w + nb * 8 + g) * STR + k0 + t;
                float yr0 = sm[KR + bb], yr1 = sm[KR + bb + 4];
                float yi0 = sm[KI + bb], yi1 = sm[KI + bb + 4];
                float krh0 = rna(yr0), krl0 = yr0 - krh0;
                float krh1 = rna(yr1), krl1 = yr1 - krh1;
                float kih0 = rna(yi0), kil0 = yi0 - kih0;
                float kih1 = rna(yi1), kil1 = yi1 - kih1;
                float ys0 = yr0 + yi0, ys1 = yr1 + yi1;
                float ksh0 = rna(ys0), ksl0 = ys0 - ksh0;
                float ksh1 = rna(ys1), ksl1 = ys1 - ksh1;
                mma8(crr[nb], qrh0, qrh1, qrh2, qrh3, krh0, krh1);
                mma8(crr[nb], qrl0, qrl1, qrl2, qrl3, krh0, krh1);
                mma8(crr[nb], qrh0, qrh1, qrh2, qrh3, krl0, krl1);
                mma8(cii[nb], qih0, qih1, qih2, qih3, kih0, kih1);
                mma8(cii[nb], qil0, qil1, qil2, qil3, kih0, kih1);
                mma8(cii[nb], qih0, qih1, qih2, qih3, kil0, kil1);
                mma8(css[nb], qsh0, qsh1, qsh2, qsh3, ksh0, ksh1);
                mma8(css[nb], qsl0, qsl1, qsl2, qsl3, ksh0, ksh1);
                mma8(css[nb], qsh0, qsh1, qsh2, qsh3, ksl0, ksl1);
            }
        }

        // ---- epilogue: scale + leaky + causal mask -> W (fp32) ----
        #pragma unroll
        for (int nb = 0; nb < 4; ++nb) {
            float vr_[4], vi_[4];
            #pragma unroll
            for (int r = 0; r < 4; ++r) {
                int il = i0w + g + ((r & 2) ? 8 : 0);
                int jg = kt + j0w + nb * 8 + 2 * t + (r & 1);
                float sr = (crr[nb][r] - cii[nb][r]) * scale;
                float si = (css[nb][r] - crr[nb][r] - cii[nb][r]) * scale;
                sr = sr >= 0.f ? sr : 0.01f * sr;
                si = si >= 0.f ? si : 0.01f * si;
                if (jg > qi0 + il) { sr = 0.f; si = 0.f; }
                vr_[r] = sr; vi_[r] = si;
            }
            int wb = (i0w + g) * STR + j0w + nb * 8 + 2 * t;
            *(float2*)&sm[WR + wb]           = make_float2(vr_[0], vr_[1]);
            *(float2*)&sm[WR + wb + 8 * STR] = make_float2(vr_[2], vr_[3]);
            *(float2*)&sm[WI + wb]           = make_float2(vi_[0], vi_[1]);
            *(float2*)&sm[WI + wb + 8 * STR] = make_float2(vi_[2], vi_[3]);
        }
        __syncthreads();

        // ---- phase 2: O += W V (W hi/lo, V tf32) ----
        for (int kk = 0; kk < 8; ++kk) {
            const int k0 = kk * 8;
            const int ab = (i0p + g) * STR + k0 + t;
            LDQUAD(WR, ab, zr0, zr1, zr2, zr3)
            LDQUAD(WI, ab, zi0, zi1, zi2, zi3)
            SPLIT4(zr0, zr1, zr2, zr3, wrh0, wrh1, wrh2, wrh3, wrl0, wrl1, wrl2, wrl3)
            SPLIT4(zi0, zi1, zi2, zi3, wih0, wih1, wih2, wih3, wil0, wil1, wil2, wil3)
            #pragma unroll
            for (int nb = 0; nb < 4; ++nb) {
                const int vb = (k0 + t) * VSTR + f0p + nb * 8 + g;
                float v0 = sm[VR + vb], v1 = sm[VR + vb + 4 * VSTR];
                float u0 = sm[VI + vb], u1 = sm[VI + vb + 4 * VSTR];
                mma8(o_r[nb], wrh0, wrh1, wrh2, wrh3, v0, v1);
                mma8(o_r[nb], wrl0, wrl1, wrl2, wrl3, v0, v1);
                mma8(o_i[nb], wih0, wih1, wih2, wih3, u0, u1);
                mma8(o_i[nb], wil0, wil1, wil2, wil3, u0, u1);
            }
        }
    }

    // ---- linear head via mma: out = O @ Watt^T + b ----
    __syncthreads();   // all phase-2 done before overwriting QR/KR regions
    #pragma unroll
    for (int nb = 0; nb < 4; ++nb)
        #pragma unroll
        for (int r = 0; r < 4; ++r) {
            int il = i0p + g + ((r & 2) ? 8 : 0);
            int fo = f0p + nb * 8 + 2 * t + (r & 1);
            sm[QR + il * STR + fo] = o_r[nb][r];
            sm[QI + il * STR + fo] = o_i[nb][r];
        }
    for (int idx = tid; idx < 64 * 64; idx += NT)
        sm[WATT + (idx >> 6) * STR + (idx & 63)] = Wg[idx];
    if (tid < 64) sm[BIAS + tid] = bg[tid];
    __syncthreads();

    float hr[4][4], hi_[4][4];
    #pragma unroll
    for (int nb = 0; nb < 4; ++nb)
        #pragma unroll
        for (int r = 0; r < 4; ++r) { hr[nb][r] = 0.f; hi_[nb][r] = 0.f; }

    for (int kk = 0; kk < 8; ++kk) {
        const int k0 = kk * 8;
        const int ab = (i0p + g) * STR + k0 + t;
        LDQUAD(QR, ab, pr0, pr1, pr2, pr3)
        LDQUAD(QI, ab, pi0, pi1, pi2, pi3)
        SPLIT4(pr0, pr1, pr2, pr3, orh0, orh1, orh2, orh3, orl0, orl1, orl2, orl3)
        SPLIT4(pi0, pi1, pi2, pi3, oih0, oih1, oih2, oih3, oil0, oil1, oil2, oil3)
        #pragma unroll
        for (int nb = 0; nb < 4; ++nb) {
            const int wb2 = (f0p + nb * 8 + g) * STR + k0 + t;
            float w0 = sm[WATT + wb2], w1 = sm[WATT + wb2 + 4];
            float wh0 = rna(w0), wl0 = w0 - wh0;
            float wh1 = rna(w1), wl1 = w1 - wh1;
            mma8(hr[nb], orh0, orh1, orh2, orh3, wh0, wh1);
            mma8(hr[nb], orl0, orl1, orl2, orl3, wh0, wh1);
            mma8(hr[nb], orh0, orh1, orh2, orh3, wl0, wl1);
            mma8(hi_[nb], oih0, oih1, oih2, oih3, wh0, wh1);
            mma8(hi_[nb], oil0, oil1, oil2, oil3, wh0, wh1);
            mma8(hi_[nb], oih0, oih1, oih2, oih3, wl0, wl1);
        }
    }

    float2* Ob = Og + ((size_t)b * N + qi0) * 64;
    #pragma unroll
    for (int nb = 0; nb < 4; ++nb)
        #pragma unroll
        for (int r = 0; r < 4; ++r) {
            int il = i0p + g + ((r & 2) ? 8 : 0);
            int fo = f0p + nb * 8 + 2 * t + (r & 1);
            float bb = sm[BIAS + fo];
            Ob[il * 64 + fo] = make_float2(hr[nb][r] + bb, hi_[nb][r] + bb);
        }
}

extern "C" void kernel_launch(void* const* d_in, const int* in_sizes, int n_in,
                              void* d_out, int out_size)
{
    const float2* Q = (const float2*)d_in[0];
    const float2* K = (const float2*)d_in[1];
    const float2* V = (const float2*)d_in[2];
    const float*  W = (const float*)d_in[3];
    const float*  bb = (const float*)d_in[4];
    float2* O = (float2*)d_out;

    static bool attr_set = false;
    if (!attr_set) {
        cudaFuncSetAttribute(attn_k, cudaFuncAttributeMaxDynamicSharedMemorySize, SMB);
        attr_set = true;
    }

    dim3 grid(4096 / 64, 4);
    attn_k<<<grid, NT, SMB>>>(Q, K, V, W, bb, O);
}